// round 2
// baseline (speedup 1.0000x reference)
#include <cuda_runtime.h>
#include <math.h>

#define BB 1024
#define DD 1024
#define NN 128
#define PT 28

// scratch (device globals — no allocation allowed)
__device__ float g_hs[PT * DD];     // silu(s*w1+b1) per step value s
__device__ float g_E[PT * DD];      // t_embed table per step value
__device__ float g_L[PT * NN];      // clean logits table
__device__ float g_S[PT * NN];      // noise std table
__device__ float g_gates[BB * NN];  // per-row gates
__device__ int   g_is64;            // timestep dtype flag

__device__ __forceinline__ int get_ts(const int* ts32, int b) {
    return g_is64 ? ts32[2 * b] : ts32[b];
}

// K0: detect int64 vs int32 timestep layout.
// int64 LE array of small nonneg values => every odd int32 word is 0.
// int32 array: odd-index timesteps ~U[0,28); all-zero prob (1/28)^1024 ~ 0.
__global__ void k_detect(const int* __restrict__ ts32) {
    int t = threadIdx.x;
    int any = 0;
    // check odd words of both possible int64 halves (covers all 1024 values)
    any |= (ts32[2 * t + 1] != 0);
    any |= (ts32[2 * (t + 512) + 1] != 0);
    any = __syncthreads_or(any);
    if (t == 0) g_is64 = !any;
}

// K1: hs[s][d] = silu(s * w1[d] + b1[d])   (s = possible timestep value)
__global__ void k_hs(const float* __restrict__ w1, const float* __restrict__ b1) {
    int i = blockIdx.x * blockDim.x + threadIdx.x;
    if (i < PT * DD) {
        int s = i / DD, d = i - s * DD;
        float x = (float)s * w1[d] + b1[d];
        g_hs[i] = x / (1.0f + expf(-x));
    }
}

// K2: E[s][j] = dot(hs[s], w2[j,:]) + b2[j].  One block per j, 28 steps at once
// so w2 (4MB) is streamed exactly once.
__global__ __launch_bounds__(256) void k_E(const float* __restrict__ w2,
                                           const float* __restrict__ b2) {
    int j = blockIdx.x, t = threadIdx.x;
    float acc[PT];
#pragma unroll
    for (int s = 0; s < PT; s++) acc[s] = 0.f;
#pragma unroll
    for (int dd = 0; dd < 4; dd++) {
        int d = t + dd * 256;
        float w = __ldg(&w2[(size_t)j * DD + d]);
#pragma unroll
        for (int s = 0; s < PT; s++) acc[s] = fmaf(g_hs[s * DD + d], w, acc[s]);
    }
#pragma unroll
    for (int s = 0; s < PT; s++)
        for (int o = 16; o > 0; o >>= 1)
            acc[s] += __shfl_xor_sync(0xffffffffu, acc[s], o);
    __shared__ float red[PT][8];
    int wid = t >> 5, lane = t & 31;
    if (lane == 0) {
#pragma unroll
        for (int s = 0; s < PT; s++) red[s][wid] = acc[s];
    }
    __syncthreads();
    if (t < PT) {
        float v = 0.f;
#pragma unroll
        for (int w8 = 0; w8 < 8; w8++) v += red[t][w8];
        g_E[t * DD + j] = v + b2[j];
    }
}

// K3: L[s][n] = dot(E[s], gate_w[n,:D]) + step*gate_w[n,D] + gate_b[n]
//     S[s][n] = softplus(dot(E[s], w_noise[:,n])) + 0.01
__global__ __launch_bounds__(256) void k_tables(const float* __restrict__ gate_w,
                                                const float* __restrict__ gate_b,
                                                const float* __restrict__ w_noise,
                                                const int* __restrict__ ts32) {
    int n = blockIdx.x, t = threadIdx.x;
    float al[PT], an[PT];
#pragma unroll
    for (int s = 0; s < PT; s++) { al[s] = 0.f; an[s] = 0.f; }
#pragma unroll
    for (int dd = 0; dd < 4; dd++) {
        int d = t + dd * 256;
        float gw = __ldg(&gate_w[(size_t)n * (DD + 1) + d]);
        float wn = __ldg(&w_noise[(size_t)d * NN + n]);
#pragma unroll
        for (int s = 0; s < PT; s++) {
            float e = g_E[s * DD + d];
            al[s] = fmaf(e, gw, al[s]);
            an[s] = fmaf(e, wn, an[s]);
        }
    }
#pragma unroll
    for (int s = 0; s < PT; s++)
        for (int o = 16; o > 0; o >>= 1) {
            al[s] += __shfl_xor_sync(0xffffffffu, al[s], o);
            an[s] += __shfl_xor_sync(0xffffffffu, an[s], o);
        }
    __shared__ float rl[PT][8], rn[PT][8];
    int wid = t >> 5, lane = t & 31;
    if (lane == 0) {
#pragma unroll
        for (int s = 0; s < PT; s++) { rl[s][wid] = al[s]; rn[s][wid] = an[s]; }
    }
    __syncthreads();
    if (t < PT) {
        float vl = 0.f, vn = 0.f;
#pragma unroll
        for (int w8 = 0; w8 < 8; w8++) { vl += rl[t][w8]; vn += rn[t][w8]; }
        float stepf = (float)get_ts(ts32, 0);
        g_L[t * NN + n] = vl + stepf * gate_w[(size_t)n * (DD + 1) + DD] + gate_b[n];
        float x = vn;
        float sp = fmaxf(x, 0.f) + log1pf(expf(-fabsf(x)));
        g_S[t * NN + n] = sp + 0.01f;
    }
}

// K4: per-row noisy top-32 softmax gating + t_embed output rows.
__global__ __launch_bounds__(128) void k_gate(const float* __restrict__ noise,
                                              const int* __restrict__ ts32,
                                              float* __restrict__ out_tembed) {
    int b = blockIdx.x, n = threadIdx.x;
    int s = get_ts(ts32, b);
    float l = g_L[s * NN + n] + noise[(size_t)b * NN + n] * g_S[s * NN + n];
    __shared__ float sl[NN];
    sl[n] = l;
    __syncthreads();
    int rank = 0;
    float mx = -INFINITY;
#pragma unroll 8
    for (int m = 0; m < NN; m++) {
        float v = sl[m];
        rank += (v > l) || (v == l && m < n);
        mx = fmaxf(mx, v);
    }
    bool sel = rank < 32;  // top-(k-1)=32 of 128 get softmaxed
    float e = sel ? expf(l - mx) : 0.f;
    __shared__ float ssum[NN];
    ssum[n] = e;
    __syncthreads();
    for (int st = 64; st > 0; st >>= 1) {
        if (n < st) ssum[n] += ssum[n + st];
        __syncthreads();
    }
    g_gates[(size_t)b * NN + n] = sel ? e / ssum[0] : 0.f;
    // t_embed[b] = E[timestep[b]]  (vectorized copy)
    const float4* er = (const float4*)&g_E[s * DD];
    float4* tr = (float4*)(out_tembed + (size_t)b * DD);
    tr[n] = er[n];
    tr[n + NN] = er[n + NN];
}

// K5: out[b,n,:] = prompts[step][n,:] * gates[b,n].  8 b-rows per block so the
// prompt row (4KB) is read once per 32KB of stores.
__global__ __launch_bounds__(256) void k_out(const float* __restrict__ pe,
                                             const int* __restrict__ ts32,
                                             float* __restrict__ out) {
    int n = blockIdx.x;        // 0..127
    int b0 = blockIdx.y * 8;   // 8 batch rows per block
    int t = threadIdx.x;       // 256 -> one float4 each
    int step = get_ts(ts32, 0);
    const float4* prow = (const float4*)(pe + ((size_t)step * NN + n) * DD);
    float4 v = prow[t];
    float4* o4 = (float4*)out;
#pragma unroll
    for (int bb = 0; bb < 8; bb++) {
        int b = b0 + bb;
        float g = __ldg(&g_gates[(size_t)b * NN + n]);
        float4 o = make_float4(v.x * g, v.y * g, v.z * g, v.w * g);
        o4[((size_t)b * NN + n) * (DD / 4) + t] = o;
    }
}

extern "C" void kernel_launch(void* const* d_in, const int* in_sizes, int n_in,
                              void* d_out, int out_size) {
    const float* pe      = (const float*)d_in[0];  // [28,128,1024]
    const float* w1      = (const float*)d_in[1];  // [1024]
    const float* b1      = (const float*)d_in[2];  // [1024]
    const float* w2      = (const float*)d_in[3];  // [1024,1024]
    const float* b2      = (const float*)d_in[4];  // [1024]
    const float* gate_w  = (const float*)d_in[5];  // [128,1025]
    const float* gate_b  = (const float*)d_in[6];  // [128]
    const float* w_noise = (const float*)d_in[7];  // [1024,128]
    const float* noise   = (const float*)d_in[8];  // [1024,128]
    const int*   ts32    = (const int*)d_in[9];    // [1024] int32 or int64 (detected)

    float* out        = (float*)d_out;                         // [B,N,D]
    float* out_tembed = (float*)d_out + (size_t)BB * NN * DD;  // [B,D]

    k_detect<<<1, 512>>>(ts32);
    k_hs<<<(PT * DD + 255) / 256, 256>>>(w1, b1);
    k_E<<<DD, 256>>>(w2, b2);
    k_tables<<<NN, 256>>>(gate_w, gate_b, w_noise, ts32);
    k_gate<<<BB, 128>>>(noise, ts32, out_tembed);
    k_out<<<dim3(NN, BB / 8), 256>>>(pe, ts32, out);
}

// round 3
// speedup vs baseline: 1.0536x; 1.0536x over previous
#include <cuda_runtime.h>
#include <math.h>

#define BB 1024
#define DD 1024
#define NN 128
#define PT 28
#define SG 7   // steps per table block (PT/4)

// scratch (device globals — no allocation allowed)
__device__ float g_hs[PT * DD];     // silu(s*w1+b1) per step value s
__device__ float g_E[PT * DD];      // t_embed table per step value
__device__ float g_L[PT * NN];      // clean logits table
__device__ float g_S[PT * NN];      // noise std table
__device__ float g_gates[BB * NN];  // per-row gates
__device__ int   g_is64;            // timestep dtype flag

__device__ __forceinline__ int get_ts(const int* ts32, int b) {
    return g_is64 ? ts32[2 * b] : ts32[b];
}

// K1: hs[s][d] = silu(s * w1[d] + b1[d]); last block also sniffs timestep dtype.
// int64 LE array of small nonneg values => every odd int32 word is 0.
// int32 array: odd-index timesteps ~U[0,28); all-zero prob ~0.
__global__ void k_hs(const float* __restrict__ w1, const float* __restrict__ b1,
                     const int* __restrict__ ts32) {
    if (blockIdx.x == gridDim.x - 1) {
        int t = threadIdx.x;  // 256 threads cover 512 odd words via 2 reads... use 4
        int any = 0;
#pragma unroll
        for (int r = 0; r < 4; r++) {
            int idx = t + r * 256;          // 0..1023
            if (idx < 512) { /* covered below uniformly */ }
            any |= (ts32[2 * idx + 1] != 0) && (idx < 1024);
        }
        any = __syncthreads_or(any);
        if (t == 0) g_is64 = !any;
        return;
    }
    int i = blockIdx.x * blockDim.x + threadIdx.x;
    if (i < PT * DD) {
        int s = i / DD, d = i - s * DD;
        float x = (float)s * w1[d] + b1[d];
        g_hs[i] = x / (1.0f + expf(-x));
    }
}

// K2: E[s][j] = dot(hs[s], w2[j,:]) + b2[j].  One block per j, 28 steps at once
// so w2 (4MB) is streamed exactly once; hs stays L1-resident across blocks.
__global__ __launch_bounds__(256) void k_E(const float* __restrict__ w2,
                                           const float* __restrict__ b2) {
    int j = blockIdx.x, t = threadIdx.x;
    float acc[PT];
#pragma unroll
    for (int s = 0; s < PT; s++) acc[s] = 0.f;
#pragma unroll
    for (int dd = 0; dd < 4; dd++) {
        int d = t + dd * 256;
        float w = __ldg(&w2[(size_t)j * DD + d]);
#pragma unroll
        for (int s = 0; s < PT; s++) acc[s] = fmaf(__ldg(&g_hs[s * DD + d]), w, acc[s]);
    }
#pragma unroll
    for (int s = 0; s < PT; s++)
        for (int o = 16; o > 0; o >>= 1)
            acc[s] += __shfl_xor_sync(0xffffffffu, acc[s], o);
    __shared__ float red[PT][8];
    int wid = t >> 5, lane = t & 31;
    if (lane == 0) {
#pragma unroll
        for (int s = 0; s < PT; s++) red[s][wid] = acc[s];
    }
    __syncthreads();
    if (t < PT) {
        float v = 0.f;
#pragma unroll
        for (int w8 = 0; w8 < 8; w8++) v += red[t][w8];
        g_E[t * DD + j] = v + b2[j];
    }
}

// K3: L[s][n] = dot(E[s], gate_w[n,:D]) + step*gate_w[n,D] + gate_b[n]
//     S[s][n] = softplus(dot(E[s], w_noise[:,n])) + 0.01
// Split over 4 step-groups of 7 for occupancy / short dep chains.
__global__ __launch_bounds__(256) void k_tables(const float* __restrict__ gate_w,
                                                const float* __restrict__ gate_b,
                                                const float* __restrict__ w_noise,
                                                const int* __restrict__ ts32) {
    int n = blockIdx.x, t = threadIdx.x;
    int s0 = blockIdx.y * SG;
    float al[SG], an[SG];
#pragma unroll
    for (int s = 0; s < SG; s++) { al[s] = 0.f; an[s] = 0.f; }
#pragma unroll
    for (int dd = 0; dd < 4; dd++) {
        int d = t + dd * 256;
        float gw = __ldg(&gate_w[(size_t)n * (DD + 1) + d]);
        float wn = __ldg(&w_noise[(size_t)d * NN + n]);
#pragma unroll
        for (int s = 0; s < SG; s++) {
            float e = __ldg(&g_E[(s0 + s) * DD + d]);
            al[s] = fmaf(e, gw, al[s]);
            an[s] = fmaf(e, wn, an[s]);
        }
    }
#pragma unroll
    for (int s = 0; s < SG; s++)
        for (int o = 16; o > 0; o >>= 1) {
            al[s] += __shfl_xor_sync(0xffffffffu, al[s], o);
            an[s] += __shfl_xor_sync(0xffffffffu, an[s], o);
        }
    __shared__ float rl[SG][8], rn[SG][8];
    int wid = t >> 5, lane = t & 31;
    if (lane == 0) {
#pragma unroll
        for (int s = 0; s < SG; s++) { rl[s][wid] = al[s]; rn[s][wid] = an[s]; }
    }
    __syncthreads();
    if (t < SG) {
        float vl = 0.f, vn = 0.f;
#pragma unroll
        for (int w8 = 0; w8 < 8; w8++) { vl += rl[t][w8]; vn += rn[t][w8]; }
        int s = s0 + t;
        float stepf = (float)get_ts(ts32, 0);
        g_L[s * NN + n] = vl + stepf * gate_w[(size_t)n * (DD + 1) + DD] + gate_b[n];
        float x = vn;
        float sp = fmaxf(x, 0.f) + log1pf(expf(-fabsf(x)));
        g_S[s * NN + n] = sp + 0.01f;
    }
}

// K4: per-row noisy top-32 softmax gating + t_embed output rows.
__global__ __launch_bounds__(128) void k_gate(const float* __restrict__ noise,
                                              const int* __restrict__ ts32,
                                              float* __restrict__ out_tembed) {
    int b = blockIdx.x, n = threadIdx.x;
    int s = get_ts(ts32, b);
    float l = g_L[s * NN + n] + noise[(size_t)b * NN + n] * g_S[s * NN + n];
    __shared__ float sl[NN];
    sl[n] = l;
    __syncthreads();
    int rank = 0;
    float mx = -INFINITY;
#pragma unroll 8
    for (int m = 0; m < NN; m++) {
        float v = sl[m];
        rank += (v > l) || (v == l && m < n);
        mx = fmaxf(mx, v);
    }
    bool sel = rank < 32;  // top-(k-1)=32 of 128 get softmaxed
    float e = sel ? expf(l - mx) : 0.f;
    __shared__ float ssum[NN];
    ssum[n] = e;
    __syncthreads();
    for (int st = 64; st > 0; st >>= 1) {
        if (n < st) ssum[n] += ssum[n + st];
        __syncthreads();
    }
    g_gates[(size_t)b * NN + n] = sel ? e / ssum[0] : 0.f;
    // t_embed[b] = E[timestep[b]]  (vectorized streaming copy)
    const float4* er = (const float4*)&g_E[s * DD];
    float4* tr = (float4*)(out_tembed + (size_t)b * DD);
    __stcs(&tr[n], er[n]);
    __stcs(&tr[n + NN], er[n + NN]);
}

// K5: out[b,n,:] = prompts[step][n,:] * gates[b,n].  16 b-rows per block so the
// prompt row (4KB) is read once per 64KB of streaming stores.
__global__ __launch_bounds__(256) void k_out(const float* __restrict__ pe,
                                             const int* __restrict__ ts32,
                                             float* __restrict__ out) {
    int n = blockIdx.x;         // 0..127
    int b0 = blockIdx.y * 16;   // 16 batch rows per block
    int t = threadIdx.x;        // 256 -> one float4 each
    int step = get_ts(ts32, 0);
    const float4* prow = (const float4*)(pe + ((size_t)step * NN + n) * DD);
    float4 v = __ldg(&prow[t]);
    float4* o4 = (float4*)out;
#pragma unroll
    for (int bb = 0; bb < 16; bb++) {
        int b = b0 + bb;
        float g = __ldg(&g_gates[(size_t)b * NN + n]);
        float4 o = make_float4(v.x * g, v.y * g, v.z * g, v.w * g);
        __stcs(&o4[((size_t)b * NN + n) * (DD / 4) + t], o);
    }
}

extern "C" void kernel_launch(void* const* d_in, const int* in_sizes, int n_in,
                              void* d_out, int out_size) {
    const float* pe      = (const float*)d_in[0];  // [28,128,1024]
    const float* w1      = (const float*)d_in[1];  // [1024]
    const float* b1      = (const float*)d_in[2];  // [1024]
    const float* w2      = (const float*)d_in[3];  // [1024,1024]
    const float* b2      = (const float*)d_in[4];  // [1024]
    const float* gate_w  = (const float*)d_in[5];  // [128,1025]
    const float* gate_b  = (const float*)d_in[6];  // [128]
    const float* w_noise = (const float*)d_in[7];  // [1024,128]
    const float* noise   = (const float*)d_in[8];  // [1024,128]
    const int*   ts32    = (const int*)d_in[9];    // [1024] int32 or int64 (detected)

    float* out        = (float*)d_out;                         // [B,N,D]
    float* out_tembed = (float*)d_out + (size_t)BB * NN * DD;  // [B,D]

    // k_hs: PT*DD/256 = 112 work blocks + 1 detect block
    k_hs<<<(PT * DD + 255) / 256 + 1, 256>>>(w1, b1, ts32);
    k_E<<<DD, 256>>>(w2, b2);
    k_tables<<<dim3(NN, PT / SG), 256>>>(gate_w, gate_b, w_noise, ts32);
    k_gate<<<BB, 128>>>(noise, ts32, out_tembed);
    k_out<<<dim3(NN, BB / 16), 256>>>(pe, ts32, out);
}